// round 7
// baseline (speedup 1.0000x reference)
#include <cuda_runtime.h>
#include <cuda_bf16.h>
#include <stdint.h>
#include <math.h>

// Problem constants
#define NB 8
#define NT 2048
#define NC 1024
#define NH 16
#define NN 64
#define NBT   (NB*NT)        // 16384 rows
#define NBTC  (NB*NT*NC)     // 16777216 elements

// ---------------------------------------------------------------------------
// Scratch. Split-bf16 buffers are PLANE-SEPARATED: viewing a buffer of
// unsigned[n] as __nv_bfloat16[2n], halves [0,n) are the hi plane and
// [n,2n) the lo plane.
// ---------------------------------------------------------------------------
__device__ float g_bR[NBTC], g_bK[NBTC], g_bV[NBTC], g_bW[NBTC];
__device__ float g_bA[NBTC], g_bM[NBTC], g_bG[NBTC], g_bY[NBTC];
__device__ unsigned g_Hw[NBT*64], g_Ha[NBT*64], g_Hg[NBT*128], g_Hv[NBT*32];
__device__ unsigned g_AxR[NBTC], g_AxK[NBTC], g_AxV[NBTC];
__device__ unsigned g_WbR[NC*NC], g_WbK[NC*NC], g_WbV[NC*NC], g_WbO[NC*NC];
__device__ unsigned g_W2d[64*NC], g_W2a[64*NC], g_W2g[128*NC], g_W2v[32*NC];

// ---------------------------------------------------------------------------
// split helpers: v -> (hi bf16, lo bf16)
// ---------------------------------------------------------------------------
__device__ __forceinline__ void split1(float v, unsigned& h, unsigned& l) {
    __nv_bfloat16 hb = __float2bfloat16(v);
    float hf = __bfloat162float(hb);
    __nv_bfloat16 lb = __float2bfloat16(v - hf);
    h = (unsigned)__bfloat16_as_ushort(hb);
    l = (unsigned)__bfloat16_as_ushort(lb);
}
// 4 floats -> hi uint2 (4 halves) + lo uint2
__device__ __forceinline__ void split4(float4 v, uint2& hi, uint2& lo) {
    unsigned h0,l0,h1,l1,h2,l2,h3,l3;
    split1(v.x,h0,l0); split1(v.y,h1,l1);
    split1(v.z,h2,l2); split1(v.w,h3,l3);
    hi = make_uint2(h0 | (h1<<16), h2 | (h3<<16));
    lo = make_uint2(l0 | (l1<<16), l2 | (l3<<16));
}

// Mix + split-pack (plane-separated) for the three big projections.
__global__ void mix3_pack_kernel(const float* __restrict__ x,
    const float* __restrict__ mr, const float* __restrict__ mk,
    const float* __restrict__ mv,
    __nv_bfloat16* __restrict__ Ar, __nv_bfloat16* __restrict__ Ak,
    __nv_bfloat16* __restrict__ Av)
{
    int i4 = blockIdx.x * blockDim.x + threadIdx.x;
    if (i4 >= NBTC/4) return;
    int idx = i4 * 4;
    int c = idx & (NC-1);
    int t = (idx / NC) % NT;

    float4 xc = *reinterpret_cast<const float4*>(x + idx);
    float4 xp = make_float4(0.f,0.f,0.f,0.f);
    if (t > 0) xp = *reinterpret_cast<const float4*>(x + idx - NC);
    float4 dx = make_float4(xp.x-xc.x, xp.y-xc.y, xp.z-xc.z, xp.w-xc.w);

    float4 m, o; uint2 hi, lo;
    m = *reinterpret_cast<const float4*>(mr + c);
    o = make_float4(xc.x + dx.x*m.x, xc.y + dx.y*m.y,
                    xc.z + dx.z*m.z, xc.w + dx.w*m.w);
    split4(o, hi, lo);
    *reinterpret_cast<uint2*>(Ar + idx) = hi;
    *reinterpret_cast<uint2*>(Ar + NBTC + idx) = lo;

    m = *reinterpret_cast<const float4*>(mk + c);
    o = make_float4(xc.x + dx.x*m.x, xc.y + dx.y*m.y,
                    xc.z + dx.z*m.z, xc.w + dx.w*m.w);
    split4(o, hi, lo);
    *reinterpret_cast<uint2*>(Ak + idx) = hi;
    *reinterpret_cast<uint2*>(Ak + NBTC + idx) = lo;

    m = *reinterpret_cast<const float4*>(mv + c);
    o = make_float4(xc.x + dx.x*m.x, xc.y + dx.y*m.y,
                    xc.z + dx.z*m.z, xc.w + dx.w*m.w);
    split4(o, hi, lo);
    *reinterpret_cast<uint2*>(Av + idx) = hi;
    *reinterpret_cast<uint2*>(Av + NBTC + idx) = lo;
}

// Plain split-pack (weights); plane = element count of the buffer.
__global__ void pack_kernel(const float* __restrict__ src,
                            __nv_bfloat16* __restrict__ dst,
                            int n4, int plane)
{
    int i4 = blockIdx.x * blockDim.x + threadIdx.x;
    if (i4 >= n4) return;
    int idx = i4 * 4;
    float4 v = *reinterpret_cast<const float4*>(src + idx);
    uint2 hi, lo;
    split4(v, hi, lo);
    *reinterpret_cast<uint2*>(dst + idx) = hi;
    *reinterpret_cast<uint2*>(dst + plane + idx) = lo;
}

// ---------------------------------------------------------------------------
// Tensor-core GEMM, split-bf16 single K-pass, cp.async 2-stage pipeline.
// C[M,N](fp32) = A'[M,K] @ B'[K,N] where A' = Ahi+Alo etc. (hi*hi + lo*hi +
// hi*lo per fragment). A,B plane-separated bf16 (lo plane at +M*K / +K*N).
// Tiles: 128x128x32, 8 warps (4x2), per-warp 32x64 via m16n8k16.
// ---------------------------------------------------------------------------
#define TBM 128
#define TBN 128
#define TBK 32
#define ASTR 40                    // halves per A-smem row
#define BSTR 136                   // halves per B-smem row
#define SA   (TBM*ASTR)            // 5120 halves per A plane
#define SB   (TBK*BSTR)            // 4352 halves per B plane
#define STAGE_H (2*SA + 2*SB)      // 18944 halves per stage
#define GEMM_SMEM (2 * STAGE_H * 2)  // bytes: 75776

__device__ __forceinline__ unsigned cvta_s(const void* p) {
    return (unsigned)__cvta_generic_to_shared(p);
}
__device__ __forceinline__ void cp16(void* dst, const void* src) {
    asm volatile("cp.async.cg.shared.global [%0], [%1], 16;"
                 :: "r"(cvta_s(dst)), "l"(src));
}
__device__ __forceinline__ void ldsm_x4(unsigned& a0, unsigned& a1,
                                        unsigned& a2, unsigned& a3,
                                        unsigned addr) {
    asm volatile("ldmatrix.sync.aligned.m8n8.x4.shared.b16 {%0,%1,%2,%3},[%4];"
                 : "=r"(a0), "=r"(a1), "=r"(a2), "=r"(a3) : "r"(addr));
}
__device__ __forceinline__ void ldsm_x2_t(unsigned& b0, unsigned& b1,
                                          unsigned addr) {
    asm volatile("ldmatrix.sync.aligned.m8n8.x2.trans.shared.b16 {%0,%1},[%2];"
                 : "=r"(b0), "=r"(b1) : "r"(addr));
}
__device__ __forceinline__ void mma_bf16(float* d, const unsigned* a,
                                         const unsigned* b) {
    asm volatile(
        "mma.sync.aligned.m16n8k16.row.col.f32.bf16.bf16.f32 "
        "{%0,%1,%2,%3},{%4,%5,%6,%7},{%8,%9},{%0,%1,%2,%3};"
        : "+f"(d[0]), "+f"(d[1]), "+f"(d[2]), "+f"(d[3])
        : "r"(a[0]), "r"(a[1]), "r"(a[2]), "r"(a[3]), "r"(b[0]), "r"(b[1]));
}

__global__ void __launch_bounds__(256) bf16gemm_kernel(
    const __nv_bfloat16* __restrict__ A, const __nv_bfloat16* __restrict__ B,
    float* __restrict__ C, int M, int N, int K)
{
    extern __shared__ __align__(16) __nv_bfloat16 smem[];

    const size_t aPlane = (size_t)M * K;
    const size_t bPlane = (size_t)K * N;
    const int tid  = threadIdx.x;
    const int lane = tid & 31;
    const int wid  = tid >> 5;
    const int warp_m = wid >> 1;
    const int warp_n = wid & 1;
    const int row0 = blockIdx.y * TBM;
    const int col0 = blockIdx.x * TBN;
    const int nkt = K / TBK;

    // stage s plane bases (halves)
    auto sAH = [&](int s) { return smem + s * STAGE_H; };
    auto sAL = [&](int s) { return smem + s * STAGE_H + SA; };
    auto sBH = [&](int s) { return smem + s * STAGE_H + 2*SA; };
    auto sBL = [&](int s) { return smem + s * STAGE_H + 2*SA + SB; };

    auto load_stage = [&](int s, int kt) {
        // A: 1024 16B-chunks (2 planes x 128 rows x 4 chunks)
#pragma unroll
        for (int i = 0; i < 4; ++i) {
            int cch = tid + i * 256;
            int plane = cch >> 9;
            int rem = cch & 511;
            int r = rem >> 2;
            int j = (rem & 3) * 8;
            const __nv_bfloat16* src = A + plane * aPlane +
                (size_t)(row0 + r) * K + kt * TBK + j;
            __nv_bfloat16* dst = (plane ? sAL(s) : sAH(s)) + r * ASTR + j;
            cp16(dst, src);
        }
        // B: 1024 16B-chunks (2 planes x 32 rows x 16 chunks)
#pragma unroll
        for (int i = 0; i < 4; ++i) {
            int cch = tid + i * 256;
            int plane = cch >> 9;
            int rem = cch & 511;
            int kr = rem >> 4;
            int j = (rem & 15) * 8;
            const __nv_bfloat16* src = B + plane * bPlane +
                (size_t)(kt * TBK + kr) * N + col0 + j;
            __nv_bfloat16* dst = (plane ? sBL(s) : sBH(s)) + kr * BSTR + j;
            cp16(dst, src);
        }
        asm volatile("cp.async.commit_group;");
    };

    float acc[2][8][4];
#pragma unroll
    for (int mt = 0; mt < 2; ++mt)
#pragma unroll
        for (int nt = 0; nt < 8; ++nt)
#pragma unroll
            for (int qq = 0; qq < 4; ++qq) acc[mt][nt][qq] = 0.f;

    load_stage(0, 0);
    for (int kt = 0; kt < nkt; ++kt) {
        const int cur = kt & 1;
        if (kt + 1 < nkt) {
            load_stage(cur ^ 1, kt + 1);
            asm volatile("cp.async.wait_group 1;");
        } else {
            asm volatile("cp.async.wait_group 0;");
        }
        __syncthreads();

        const __nv_bfloat16* AH = sAH(cur);
        const __nv_bfloat16* AL = sAL(cur);
        const __nv_bfloat16* BH = sBH(cur);
        const __nv_bfloat16* BL = sBL(cur);
#pragma unroll
        for (int ks = 0; ks < 2; ++ks) {
            unsigned aH[2][4], aL[2][4];
#pragma unroll
            for (int mt = 0; mt < 2; ++mt) {
                int r = warp_m * 32 + mt * 16 + (lane & 15);
                int c = ks * 16 + (lane >> 4) * 8;
                ldsm_x4(aH[mt][0], aH[mt][1], aH[mt][2], aH[mt][3],
                        cvta_s(AH + r * ASTR + c));
                ldsm_x4(aL[mt][0], aL[mt][1], aL[mt][2], aL[mt][3],
                        cvta_s(AL + r * ASTR + c));
            }
#pragma unroll
            for (int nt = 0; nt < 8; ++nt) {
                int kr = ks * 16 + (lane & 15);
                int nc = warp_n * 64 + nt * 8;
                unsigned bH[2], bL[2];
                ldsm_x2_t(bH[0], bH[1], cvta_s(BH + kr * BSTR + nc));
                ldsm_x2_t(bL[0], bL[1], cvta_s(BL + kr * BSTR + nc));
#pragma unroll
                for (int mt = 0; mt < 2; ++mt) {
                    mma_bf16(acc[mt][nt], aH[mt], bH);
                    mma_bf16(acc[mt][nt], aL[mt], bH);
                    mma_bf16(acc[mt][nt], aH[mt], bL);
                }
            }
        }
        __syncthreads();
    }

    const int g = lane >> 2, tig = lane & 3;
#pragma unroll
    for (int mt = 0; mt < 2; ++mt) {
        int r0 = row0 + warp_m * 32 + mt * 16 + g;
#pragma unroll
        for (int nt = 0; nt < 8; ++nt) {
            int c0 = col0 + warp_n * 64 + nt * 8 + 2 * tig;
            *reinterpret_cast<float2*>(C + (size_t)r0 * N + c0) =
                make_float2(acc[mt][nt][0], acc[mt][nt][1]);
            *reinterpret_cast<float2*>(C + (size_t)(r0 + 8) * N + c0) =
                make_float2(acc[mt][nt][2], acc[mt][nt][3]);
        }
    }
}

// ---------------------------------------------------------------------------
// SIMT SGEMM (LoRA first stages): fp32 math; MIX fuses time-shift; ACT
// epilogue; PACK emits plane-separated split-bf16 (plane = M*N elements).
// ---------------------------------------------------------------------------
template<int ACT>
__device__ __forceinline__ float actf(float v) {
    if (ACT == 1) return tanhf(v);
    if (ACT == 2) return 1.f / (1.f + expf(-v));
    return v;
}

template<int BM, int BN, int BK, int TM, int TN, int ACT, bool MIX, bool PACK>
__global__ void __launch_bounds__((BM/TM)*(BN/TN))
sgemm_kernel(const float* __restrict__ A, const float* __restrict__ Mv,
             const float* __restrict__ B,
             void* __restrict__ Cv, int M, int N, int K)
{
    constexpr int THREADS = (BM/TM)*(BN/TN);
    __shared__ float As[BK][BM];
    __shared__ float Bs[BK][BN];

    const int tid  = threadIdx.x;
    const int row0 = blockIdx.y * BM;
    const int col0 = blockIdx.x * BN;
    const int trow = tid / (BN/TN);
    const int tcol = tid % (BN/TN);
    const size_t planeC = (size_t)M * N;

    float acc[TM][TN];
#pragma unroll
    for (int i = 0; i < TM; ++i)
#pragma unroll
        for (int j = 0; j < TN; ++j) acc[i][j] = 0.f;

    const int nkt = K / BK;
    for (int kt = 0; kt < nkt; ++kt) {
        const int k0 = kt * BK;
        for (int idx = tid; idx < BM*(BK/4); idx += THREADS) {
            int r  = idx / (BK/4);
            int kk = (idx % (BK/4)) * 4;
            int grow = row0 + r;
            const float* ap = A + (size_t)grow * K + k0 + kk;
            float4 v = *reinterpret_cast<const float4*>(ap);
            if (MIX) {
                float4 m = *reinterpret_cast<const float4*>(Mv + k0 + kk);
                float4 xp = make_float4(0.f, 0.f, 0.f, 0.f);
                if ((grow & (NT-1)) != 0)
                    xp = *reinterpret_cast<const float4*>(ap - K);
                v.x += (xp.x - v.x) * m.x;
                v.y += (xp.y - v.y) * m.y;
                v.z += (xp.z - v.z) * m.z;
                v.w += (xp.w - v.w) * m.w;
            }
            As[kk+0][r] = v.x; As[kk+1][r] = v.y;
            As[kk+2][r] = v.z; As[kk+3][r] = v.w;
        }
        for (int idx = tid; idx < BK*(BN/4); idx += THREADS) {
            int r  = idx / (BN/4);
            int cc = (idx % (BN/4)) * 4;
            int gc = col0 + cc;
            float4 v = make_float4(0.f,0.f,0.f,0.f);
            if (gc < N) v = *reinterpret_cast<const float4*>(
                B + (size_t)(k0 + r) * N + gc);
            *reinterpret_cast<float4*>(&Bs[r][cc]) = v;
        }
        __syncthreads();

#pragma unroll
        for (int k = 0; k < BK; ++k) {
            float ar[TM], br[TN];
#pragma unroll
            for (int i = 0; i < TM; i += 4) {
                float4 t = *reinterpret_cast<const float4*>(&As[k][trow*TM + i]);
                ar[i] = t.x; ar[i+1] = t.y; ar[i+2] = t.z; ar[i+3] = t.w;
            }
#pragma unroll
            for (int j = 0; j < TN; j += 4) {
                float4 t = *reinterpret_cast<const float4*>(&Bs[k][tcol*TN + j]);
                br[j] = t.x; br[j+1] = t.y; br[j+2] = t.z; br[j+3] = t.w;
            }
#pragma unroll
            for (int i = 0; i < TM; ++i)
#pragma unroll
                for (int j = 0; j < TN; ++j)
                    acc[i][j] += ar[i] * br[j];
        }
        __syncthreads();
    }
#pragma unroll
    for (int i = 0; i < TM; ++i) {
        size_t gr = (size_t)(row0 + trow*TM + i);
#pragma unroll
        for (int j = 0; j < TN; j += 4) {
            int gc = col0 + tcol*TN + j;
            if (gc < N) {
                float4 v = make_float4(actf<ACT>(acc[i][j+0]),
                                       actf<ACT>(acc[i][j+1]),
                                       actf<ACT>(acc[i][j+2]),
                                       actf<ACT>(acc[i][j+3]));
                if (PACK) {
                    uint2 hi, lo;
                    split4(v, hi, lo);
                    __nv_bfloat16* Cp = (__nv_bfloat16*)Cv;
                    *reinterpret_cast<uint2*>(Cp + gr * N + gc) = hi;
                    *reinterpret_cast<uint2*>(Cp + planeC + gr * N + gc) = lo;
                } else {
                    *reinterpret_cast<float4*>((float*)Cv + gr * N + gc) = v;
                }
            }
        }
    }
}

// ---------------------------------------------------------------------------
// Pre-recurrence fusion (warp = one (b,t,h) head; lane = 2 channels).
// IN-PLACE: Wd over Wp, K2 over Kr, Vf over Vr, AA over Ap, BB over Vm.
// ---------------------------------------------------------------------------
__device__ __forceinline__ float warp_sum(float v) {
#pragma unroll
    for (int o = 16; o > 0; o >>= 1) v += __shfl_xor_sync(0xffffffffu, v, o);
    return v;
}
__device__ __forceinline__ float sigmoidf_(float v) { return 1.f / (1.f + expf(-v)); }
__device__ __forceinline__ float softplusf_(float z) {
    return fmaxf(z, 0.f) + log1pf(expf(-fabsf(z)));
}

__global__ void fuse_pre_kernel(
    const float* v0,
    const float* td, const float* taa, const float* tmv,
    const float* tkkk, const float* tma,
    float* bK, float* bV, float* bW, float* bA, float* bM)
{
    int gw = blockIdx.x * (blockDim.x >> 5) + (threadIdx.x >> 5);
    if (gw >= NBT * NH) return;
    int lane = threadIdx.x & 31;
    int h  = gw & (NH - 1);
    int bt = gw >> 4;
    size_t idx = (size_t)bt * NC + h * 64 + lane * 2;
    int c = h * 64 + lane * 2;

    float2 kr  = *reinterpret_cast<const float2*>(bK + idx);
    float2 vr  = *reinterpret_cast<const float2*>(bV + idx);
    float2 wp  = *reinterpret_cast<const float2*>(bW + idx);
    float2 ap  = *reinterpret_cast<const float2*>(bA + idx);
    float2 vm  = *reinterpret_cast<const float2*>(bM + idx);
    float2 v0v = *reinterpret_cast<const float2*>(v0 + idx);
    float2 tdv = *reinterpret_cast<const float2*>(td + c);
    float2 tav = *reinterpret_cast<const float2*>(taa + c);
    float2 tmvv= *reinterpret_cast<const float2*>(tmv + c);
    float2 tkv = *reinterpret_cast<const float2*>(tkkk + c);
    float2 tmav= *reinterpret_cast<const float2*>(tma + c);

    float u0 = tdv.x + wp.x, u1 = tdv.y + wp.y;
    float w0 = -softplusf_(-u0) - 0.5f, w1 = -softplusf_(-u1) - 0.5f;
    float2 wd = make_float2(expf(-expf(w0)), expf(-expf(w1)));
    float as0 = sigmoidf_(tav.x + ap.x), as1 = sigmoidf_(tav.y + ap.y);
    float vs0 = sigmoidf_(tmvv.x + vm.x), vs1 = sigmoidf_(tmvv.y + vm.y);
    float2 vf = make_float2(vr.x + (v0v.x - vr.x) * vs0,
                            vr.y + (v0v.y - vr.y) * vs1);
    float kt0 = kr.x * tkv.x, kt1 = kr.y * tkv.y;
    float ss = warp_sum(kt0*kt0 + kt1*kt1);
    float inv = 1.f / fmaxf(sqrtf(ss), 1e-12f);
    float kk0 = kt0 * inv, kk1 = kt1 * inv;

    float2 aa = make_float2(-kk0, -kk1);
    float2 bb = make_float2(kk0 * as0, kk1 * as1);
    float2 k2 = make_float2(kr.x * (1.f + (as0 - 1.f) * tmav.x),
                            kr.y * (1.f + (as1 - 1.f) * tmav.y));

    *reinterpret_cast<float2*>(bW + idx) = wd;
    *reinterpret_cast<float2*>(bK + idx) = k2;
    *reinterpret_cast<float2*>(bV + idx) = vf;
    *reinterpret_cast<float2*>(bA + idx) = aa;
    *reinterpret_cast<float2*>(bM + idx) = bb;
}

// ---------------------------------------------------------------------------
// RWKV7 recurrence. One CTA per (b,h); 256 threads: i = tid>>2 (state row),
// quarter = tid&3 (16 state cols in registers). shfl_xor(1)+(2) closes the
// sa / out dot products across the 4 lanes of a row.
// ---------------------------------------------------------------------------
__global__ void __launch_bounds__(256) wkv7_kernel(
    const float* __restrict__ R,  const float* __restrict__ Wd,
    const float* __restrict__ K2, const float* __restrict__ V,
    const float* __restrict__ AA, const float* __restrict__ BB,
    float* __restrict__ Y)
{
    const int bh = blockIdx.x;
    const int b = bh / NH, h = bh % NH;
    const int tid = threadIdx.x;
    const int i = tid >> 2;          // row 0..63
    const int qc = tid & 3;          // column quarter
    const int role = tid >> 6;       // load role 0..3
    const int lj = tid & 63;

    __shared__ float sm[2][6][64];
    float st[16];
#pragma unroll
    for (int j = 0; j < 16; ++j) st[j] = 0.f;

    const size_t base = (size_t)b * NT * NC + (size_t)h * 64;

    if (role == 0)      { sm[0][0][lj] = R [base + lj]; sm[0][4][lj] = AA[base + lj]; }
    else if (role == 1) { sm[0][1][lj] = Wd[base + lj]; sm[0][5][lj] = BB[base + lj]; }
    else if (role == 2) { sm[0][2][lj] = K2[base + lj]; }
    else                { sm[0][3][lj] = V [base + lj]; }

    const int jb = qc * 16;
    for (int t = 0; t < NT; ++t) {
        __syncthreads();
        const int cur = t & 1;
        if (t + 1 < NT) {
            const size_t nb = base + (size_t)(t + 1) * NC;
            const int nxt = cur ^ 1;
            if (role == 0)      { sm[nxt][0][lj] = R [nb + lj]; sm[nxt][4][lj] = AA[nb + lj]; }
            else if (role == 1) { sm[nxt][1][lj] = Wd[nb + lj]; sm[nxt][5][lj] = BB[nb + lj]; }
            else if (role == 2) { sm[nxt][2][lj] = K2[nb + lj]; }
            else                { sm[nxt][3][lj] = V [nb + lj]; }
        }
        const float4* rs4 = reinterpret_cast<const float4*>(&sm[cur][0][jb]);
        const float4* ws4 = reinterpret_cast<const float4*>(&sm[cur][1][jb]);
        const float4* ks4 = reinterpret_cast<const float4*>(&sm[cur][2][jb]);
        const float4* as4 = reinterpret_cast<const float4*>(&sm[cur][4][jb]);
        const float4* bs4 = reinterpret_cast<const float4*>(&sm[cur][5][jb]);
        const float vi = sm[cur][3][i];

        float sa = 0.f;
#pragma unroll
        for (int j4 = 0; j4 < 4; ++j4) {
            float4 a = as4[j4];
            sa += st[4*j4+0]*a.x + st[4*j4+1]*a.y + st[4*j4+2]*a.z + st[4*j4+3]*a.w;
        }
        sa += __shfl_xor_sync(0xffffffffu, sa, 1);
        sa += __shfl_xor_sync(0xffffffffu, sa, 2);

        float out = 0.f;
#pragma unroll
        for (int j4 = 0; j4 < 4; ++j4) {
            float4 w = ws4[j4], bb = bs4[j4], kk = ks4[j4], rr = rs4[j4];
            float s0 = st[4*j4+0]*w.x + sa*bb.x + vi*kk.x;
            float s1 = st[4*j4+1]*w.y + sa*bb.y + vi*kk.y;
            float s2 = st[4*j4+2]*w.z + sa*bb.z + vi*kk.z;
            float s3 = st[4*j4+3]*w.w + sa*bb.w + vi*kk.w;
            st[4*j4+0] = s0; st[4*j4+1] = s1; st[4*j4+2] = s2; st[4*j4+3] = s3;
            out += s0*rr.x + s1*rr.y + s2*rr.z + s3*rr.w;
        }
        out += __shfl_xor_sync(0xffffffffu, out, 1);
        out += __shfl_xor_sync(0xffffffffu, out, 2);
        if (qc == 0) Y[base + (size_t)t * NC + i] = out;
    }
}

// ---------------------------------------------------------------------------
// Post: per-head GroupNorm + rkv bonus + gate -> plane-separated split-bf16
// ---------------------------------------------------------------------------
__global__ void post_kernel(
    const float* __restrict__ Y,  const float* __restrict__ R,
    const float* __restrict__ K2, const float* __restrict__ Vf,
    const float* __restrict__ G,  const float* __restrict__ fa,
    const float* __restrict__ lnw, const float* __restrict__ lnb,
    __nv_bfloat16* __restrict__ Y2p)
{
    int gw = blockIdx.x * (blockDim.x >> 5) + (threadIdx.x >> 5);
    if (gw >= NBT * NH) return;
    int lane = threadIdx.x & 31;
    int h  = gw & (NH - 1);
    int bt = gw >> 4;
    size_t idx = (size_t)bt * NC + h * 64 + lane * 2;
    int c = h * 64 + lane * 2;

    float2 y  = *reinterpret_cast<const float2*>(Y  + idx);
    float2 r2 = *reinterpret_cast<const float2*>(R  + idx);
    float2 k2 = *reinterpret_cast<const float2*>(K2 + idx);
    float2 vf = *reinterpret_cast<const float2*>(Vf + idx);
    float2 g2 = *reinterpret_cast<const float2*>(G  + idx);
    float2 fav = *reinterpret_cast<const float2*>(fa + c);
    float2 lw = *reinterpret_cast<const float2*>(lnw + c);
    float2 lb = *reinterpret_cast<const float2*>(lnb + c);

    float s1 = warp_sum(y.x + y.y);
    float s2 = warp_sum(y.x*y.x + y.y*y.y);
    float mu  = s1 * (1.f / 64.f);
    float var = s2 * (1.f / 64.f) - mu * mu;
    float rs  = rsqrtf(var + 6.4e-4f);

    float srkv = warp_sum(r2.x*k2.x*fav.x + r2.y*k2.y*fav.y);

    float o0 = (((y.x - mu) * rs) * lw.x + lb.x + srkv * vf.x) * g2.x;
    float o1 = (((y.y - mu) * rs) * lw.y + lb.y + srkv * vf.y) * g2.y;
    unsigned h0,l0,h1,l1;
    split1(o0,h0,l0); split1(o1,h1,l1);
    *reinterpret_cast<unsigned*>(Y2p + idx)        = h0 | (h1<<16);
    *reinterpret_cast<unsigned*>(Y2p + NBTC + idx) = l0 | (l1<<16);
}

// ---------------------------------------------------------------------------
// Host launcher
// ---------------------------------------------------------------------------
extern "C" void kernel_launch(void* const* d_in, const int* in_sizes, int n_in,
                              void* d_out, int out_size)
{
    (void)in_sizes; (void)n_in;
    const float* x     = (const float*)d_in[0];
    const float* v0    = (const float*)d_in[1];
    const float* maa_r = (const float*)d_in[2];
    const float* maa_w = (const float*)d_in[3];
    const float* maa_k = (const float*)d_in[4];
    const float* maa_v = (const float*)d_in[5];
    const float* maa_a = (const float*)d_in[6];
    const float* maa_g = (const float*)d_in[7];
    const float* tdec  = (const float*)d_in[8];
    const float* faaaa = (const float*)d_in[9];
    const float* taaaaa= (const float*)d_in[10];
    const float* dw1   = (const float*)d_in[11];
    const float* dw2   = (const float*)d_in[12];
    const float* aw1   = (const float*)d_in[13];
    const float* aw2   = (const float*)d_in[14];
    const float* gw1   = (const float*)d_in[15];
    const float* gw2   = (const float*)d_in[16];
    const float* mvw1  = (const float*)d_in[17];
    const float* mvw2  = (const float*)d_in[18];
    const float* tmv   = (const float*)d_in[19];
    const float* tkkk  = (const float*)d_in[20];
    const float* tma_  = (const float*)d_in[21];
    const float* W_r   = (const float*)d_in[22];
    const float* W_k   = (const float*)d_in[23];
    const float* W_v   = (const float*)d_in[24];
    const float* W_out = (const float*)d_in[25];
    const float* lnw   = (const float*)d_in[26];
    const float* lnb   = (const float*)d_in[27];
    float* out = (float*)d_out;

    void* q;
    float *p_R,*p_K,*p_V,*p_W,*p_A,*p_M,*p_G,*p_Y;
    __nv_bfloat16 *p_Hw,*p_Ha,*p_Hg,*p_Hv;
    __nv_bfloat16 *p_AxR,*p_AxK,*p_AxV,*p_WbR,*p_WbK,*p_WbV,*p_WbO;
    __nv_bfloat16 *p_W2d,*p_W2a,*p_W2g,*p_W2v;
    cudaGetSymbolAddress(&q, g_bR); p_R = (float*)q;
    cudaGetSymbolAddress(&q, g_bK); p_K = (float*)q;
    cudaGetSymbolAddress(&q, g_bV); p_V = (float*)q;
    cudaGetSymbolAddress(&q, g_bW); p_W = (float*)q;
    cudaGetSymbolAddress(&q, g_bA); p_A = (float*)q;
    cudaGetSymbolAddress(&q, g_bM); p_M = (float*)q;
    cudaGetSymbolAddress(&q, g_bG); p_G = (float*)q;
    cudaGetSymbolAddress(&q, g_bY); p_Y = (float*)q;
    cudaGetSymbolAddress(&q, g_Hw); p_Hw = (__nv_bfloat16*)q;
    cudaGetSymbolAddress(&q, g_Ha); p_Ha = (__nv_bfloat16*)q;
    cudaGetSymbolAddress(&q, g_Hg); p_Hg = (__nv_bfloat16*)q;
    cudaGetSymbolAddress(&q, g_Hv); p_Hv = (__nv_bfloat16*)q;
    cudaGetSymbolAddress(&q, g_AxR); p_AxR = (__nv_bfloat16*)q;
    cudaGetSymbolAddress(&q, g_AxK); p_AxK = (__nv_bfloat16*)q;
    cudaGetSymbolAddress(&q, g_AxV); p_AxV = (__nv_bfloat16*)q;
    cudaGetSymbolAddress(&q, g_WbR); p_WbR = (__nv_bfloat16*)q;
    cudaGetSymbolAddress(&q, g_WbK); p_WbK = (__nv_bfloat16*)q;
    cudaGetSymbolAddress(&q, g_WbV); p_WbV = (__nv_bfloat16*)q;
    cudaGetSymbolAddress(&q, g_WbO); p_WbO = (__nv_bfloat16*)q;
    cudaGetSymbolAddress(&q, g_W2d); p_W2d = (__nv_bfloat16*)q;
    cudaGetSymbolAddress(&q, g_W2a); p_W2a = (__nv_bfloat16*)q;
    cudaGetSymbolAddress(&q, g_W2g); p_W2g = (__nv_bfloat16*)q;
    cudaGetSymbolAddress(&q, g_W2v); p_W2v = (__nv_bfloat16*)q;

    cudaFuncSetAttribute(bf16gemm_kernel,
                         cudaFuncAttributeMaxDynamicSharedMemorySize,
                         GEMM_SMEM);

    // 1. mix + split-pack of activations; split-pack all weights
    mix3_pack_kernel<<<(NBTC/4 + 255)/256, 256>>>(x, maa_r, maa_k, maa_v,
                                                  p_AxR, p_AxK, p_AxV);
    pack_kernel<<<(NC*NC/4 + 255)/256, 256>>>(W_r,   p_WbR, NC*NC/4, NC*NC);
    pack_kernel<<<(NC*NC/4 + 255)/256, 256>>>(W_k,   p_WbK, NC*NC/4, NC*NC);
    pack_kernel<<<(NC*NC/4 + 255)/256, 256>>>(W_v,   p_WbV, NC*NC/4, NC*NC);
    pack_kernel<<<(NC*NC/4 + 255)/256, 256>>>(W_out, p_WbO, NC*NC/4, NC*NC);
    pack_kernel<<<(64*NC/4 + 255)/256, 256>>>(dw2,  p_W2d, 64*NC/4, 64*NC);
    pack_kernel<<<(64*NC/4 + 255)/256, 256>>>(aw2,  p_W2a, 64*NC/4, 64*NC);
    pack_kernel<<<(128*NC/4 + 255)/256, 256>>>(gw2, p_W2g, 128*NC/4, 128*NC);
    pack_kernel<<<(32*NC/4 + 255)/256, 256>>>(mvw2, p_W2v, 32*NC/4, 32*NC);
    // 2. big projections on tensor cores (cp.async 2-stage pipeline)
    bf16gemm_kernel<<<dim3(NC/TBN, NBT/TBM), 256, GEMM_SMEM>>>(p_AxR, p_WbR, p_R, NBT, NC, NC);
    bf16gemm_kernel<<<dim3(NC/TBN, NBT/TBM), 256, GEMM_SMEM>>>(p_AxK, p_WbK, p_K, NBT, NC, NC);
    bf16gemm_kernel<<<dim3(NC/TBN, NBT/TBM), 256, GEMM_SMEM>>>(p_AxV, p_WbV, p_V, NBT, NC, NC);
    // 3. LoRA first stages (SIMT; mix fused; act fused; plane-packed output)
    sgemm_kernel<64,64,8,4,4,1,true,true><<<dim3(1,256),256>>>(x, maa_w, dw1,  p_Hw, NBT,  64, NC);
    sgemm_kernel<64,64,8,4,4,0,true,true><<<dim3(1,256),256>>>(x, maa_a, aw1,  p_Ha, NBT,  64, NC);
    sgemm_kernel<64,64,8,4,4,2,true,true><<<dim3(2,256),256>>>(x, maa_g, gw1,  p_Hg, NBT, 128, NC);
    sgemm_kernel<64,64,8,4,4,0,true,true><<<dim3(1,256),256>>>(x, maa_v, mvw1, p_Hv, NBT,  32, NC);
    // 4. LoRA second stages on tensor cores
    bf16gemm_kernel<<<dim3(NC/TBN, NBT/TBM), 256, GEMM_SMEM>>>(p_Hw, p_W2d, p_W, NBT, NC,  64);
    bf16gemm_kernel<<<dim3(NC/TBN, NBT/TBM), 256, GEMM_SMEM>>>(p_Ha, p_W2a, p_A, NBT, NC,  64);
    bf16gemm_kernel<<<dim3(NC/TBN, NBT/TBM), 256, GEMM_SMEM>>>(p_Hg, p_W2g, p_G, NBT, NC, 128);
    bf16gemm_kernel<<<dim3(NC/TBN, NBT/TBM), 256, GEMM_SMEM>>>(p_Hv, p_W2v, p_M, NBT, NC,  32);
    // 5. pre-recurrence fusion (in-place)
    fuse_pre_kernel<<<(NBT*NH)/8, 256>>>(v0, tdec, taaaaa, tmv, tkkk, tma_,
                                         p_K, p_V, p_W, p_A, p_M);
    // 6. recurrence (256 threads per head-CTA)
    wkv7_kernel<<<NB*NH, 256>>>(p_R, p_W, p_K, p_V, p_A, p_M, p_Y);
    // 7. groupnorm + rkv + gate -> plane-packed Y2 (into AxR scratch)
    post_kernel<<<(NBT*NH)/8, 256>>>(p_Y, p_R, p_K, p_V, p_G, faaaa,
                                     lnw, lnb, p_AxR);
    // 8. output projection on tensor cores
    bf16gemm_kernel<<<dim3(NC/TBN, NBT/TBM), 256, GEMM_SMEM>>>(p_AxR, p_WbO, out, NBT, NC, NC);
    // 9. second tuple element: v0 passthrough
    if (out_size >= 2*NBTC) {
        cudaMemcpyAsync(out + NBTC, v0, (size_t)NBTC * sizeof(float),
                        cudaMemcpyDeviceToDevice, 0);
    }
}

// round 10
// speedup vs baseline: 1.1393x; 1.1393x over previous
#include <cuda_runtime.h>
#include <cuda_bf16.h>
#include <stdint.h>
#include <math.h>

// Problem constants
#define NB 8
#define NT 2048
#define NC 1024
#define NH 16
#define NN 64
#define NBT   (NB*NT)        // 16384 rows
#define NBTC  (NB*NT*NC)     // 16777216 elements

// ---------------------------------------------------------------------------
// Scratch (static device globals).
//   fp32: R, K(Kr->K2), V(Vr->Vf), W(Wp->Wd), A(Ap->AA), M(Vm->BB), G, Y
//   packed split-bf16 (hi|lo per element, unsigned): AxR/AxK/AxV (mixed x;
//   AxR reused for packed Y2), Wb* (big weights), H* (LoRA hidden), W2*
// ---------------------------------------------------------------------------
__device__ float g_bR[NBTC], g_bK[NBTC], g_bV[NBTC], g_bW[NBTC];
__device__ float g_bA[NBTC], g_bM[NBTC], g_bG[NBTC], g_bY[NBTC];
__device__ unsigned g_Hw[NBT*64], g_Ha[NBT*64], g_Hg[NBT*128], g_Hv[NBT*32];
__device__ unsigned g_AxR[NBTC], g_AxK[NBTC], g_AxV[NBTC];
__device__ unsigned g_WbR[NC*NC], g_WbK[NC*NC], g_WbV[NC*NC], g_WbO[NC*NC];
__device__ unsigned g_W2d[64*NC], g_W2a[64*NC], g_W2g[128*NC], g_W2v[32*NC];

// ---------------------------------------------------------------------------
// split-bf16 packing helper
// ---------------------------------------------------------------------------
__device__ __forceinline__ unsigned packsplit(float v) {
    __nv_bfloat16 h = __float2bfloat16(v);
    float hf = __bfloat162float(h);
    __nv_bfloat16 l = __float2bfloat16(v - hf);
    unsigned hb = (unsigned)__bfloat16_as_ushort(h);
    unsigned lb = (unsigned)__bfloat16_as_ushort(l);
    return hb | (lb << 16);
}

// Mix + pack for the three big projections.
__global__ void mix3_pack_kernel(const float* __restrict__ x,
    const float* __restrict__ mr, const float* __restrict__ mk,
    const float* __restrict__ mv,
    unsigned* __restrict__ Ar, unsigned* __restrict__ Ak,
    unsigned* __restrict__ Av)
{
    int i4 = blockIdx.x * blockDim.x + threadIdx.x;
    if (i4 >= NBTC/4) return;
    int idx = i4 * 4;
    int c = idx & (NC-1);
    int t = (idx / NC) % NT;

    float4 xc = *reinterpret_cast<const float4*>(x + idx);
    float4 xp = make_float4(0.f,0.f,0.f,0.f);
    if (t > 0) xp = *reinterpret_cast<const float4*>(x + idx - NC);
    float4 dx = make_float4(xp.x-xc.x, xp.y-xc.y, xp.z-xc.z, xp.w-xc.w);

    float4 m, o;
    uint4 u;
    m = *reinterpret_cast<const float4*>(mr + c);
    o = make_float4(xc.x + dx.x*m.x, xc.y + dx.y*m.y,
                    xc.z + dx.z*m.z, xc.w + dx.w*m.w);
    u.x = packsplit(o.x); u.y = packsplit(o.y);
    u.z = packsplit(o.z); u.w = packsplit(o.w);
    *reinterpret_cast<uint4*>(Ar + idx) = u;

    m = *reinterpret_cast<const float4*>(mk + c);
    o = make_float4(xc.x + dx.x*m.x, xc.y + dx.y*m.y,
                    xc.z + dx.z*m.z, xc.w + dx.w*m.w);
    u.x = packsplit(o.x); u.y = packsplit(o.y);
    u.z = packsplit(o.z); u.w = packsplit(o.w);
    *reinterpret_cast<uint4*>(Ak + idx) = u;

    m = *reinterpret_cast<const float4*>(mv + c);
    o = make_float4(xc.x + dx.x*m.x, xc.y + dx.y*m.y,
                    xc.z + dx.z*m.z, xc.w + dx.w*m.w);
    u.x = packsplit(o.x); u.y = packsplit(o.y);
    u.z = packsplit(o.z); u.w = packsplit(o.w);
    *reinterpret_cast<uint4*>(Av + idx) = u;
}

// Plain pack (weights)
__global__ void pack_kernel(const float* __restrict__ src,
                            unsigned* __restrict__ dst, int n4)
{
    int i4 = blockIdx.x * blockDim.x + threadIdx.x;
    if (i4 >= n4) return;
    int idx = i4 * 4;
    float4 v = *reinterpret_cast<const float4*>(src + idx);
    uint4 o;
    o.x = packsplit(v.x); o.y = packsplit(v.y);
    o.z = packsplit(v.z); o.w = packsplit(v.w);
    *reinterpret_cast<uint4*>(dst + idx) = o;
}

// ---------------------------------------------------------------------------
// Tensor-core GEMM, split-bf16 single K-pass: hi/lo planes in smem, 3 MMAs
// per fragment. C[M,N](fp32) = A[M,K] @ B[K,N]; A,B packed (hi|lo) unsigned
// per element. Tiles: 128x128x32, 8 warps (4x2).
// ---------------------------------------------------------------------------
#define TBM 128
#define TBN 128
#define TBK 32
#define ASTR 40    // halves per A-smem row
#define BSTR 136   // halves per B-smem row

__device__ __forceinline__ unsigned cvta_s(const void* p) {
    return (unsigned)__cvta_generic_to_shared(p);
}
__device__ __forceinline__ void ldsm_x4(unsigned& a0, unsigned& a1,
                                        unsigned& a2, unsigned& a3,
                                        unsigned addr) {
    asm volatile("ldmatrix.sync.aligned.m8n8.x4.shared.b16 {%0,%1,%2,%3},[%4];"
                 : "=r"(a0), "=r"(a1), "=r"(a2), "=r"(a3) : "r"(addr));
}
__device__ __forceinline__ void ldsm_x2_t(unsigned& b0, unsigned& b1,
                                          unsigned addr) {
    asm volatile("ldmatrix.sync.aligned.m8n8.x2.trans.shared.b16 {%0,%1},[%2];"
                 : "=r"(b0), "=r"(b1) : "r"(addr));
}
__device__ __forceinline__ void mma_bf16(float* d, const unsigned* a,
                                         const unsigned* b) {
    asm volatile(
        "mma.sync.aligned.m16n8k16.row.col.f32.bf16.bf16.f32 "
        "{%0,%1,%2,%3},{%4,%5,%6,%7},{%8,%9},{%0,%1,%2,%3};"
        : "+f"(d[0]), "+f"(d[1]), "+f"(d[2]), "+f"(d[3])
        : "r"(a[0]), "r"(a[1]), "r"(a[2]), "r"(a[3]), "r"(b[0]), "r"(b[1]));
}

__global__ void __launch_bounds__(256) bf16gemm_kernel(
    const unsigned* __restrict__ Ap, const unsigned* __restrict__ Bp,
    float* __restrict__ C, int M, int N, int K)
{
    __shared__ __align__(16) __nv_bfloat16 AsH[TBM * ASTR];
    __shared__ __align__(16) __nv_bfloat16 AsL[TBM * ASTR];
    __shared__ __align__(16) __nv_bfloat16 BsH[TBK * BSTR];
    __shared__ __align__(16) __nv_bfloat16 BsL[TBK * BSTR];

    const int tid  = threadIdx.x;
    const int lane = tid & 31;
    const int wid  = tid >> 5;
    const int warp_m = wid >> 1;
    const int warp_n = wid & 1;
    const int row0 = blockIdx.y * TBM;
    const int col0 = blockIdx.x * TBN;

    float acc[2][8][4];
#pragma unroll
    for (int mt = 0; mt < 2; ++mt)
#pragma unroll
        for (int nt = 0; nt < 8; ++nt)
#pragma unroll
            for (int q = 0; q < 4; ++q) acc[mt][nt][q] = 0.f;

    const int nkt = K / TBK;
    for (int kt = 0; kt < nkt; ++kt) {
        __syncthreads();
#pragma unroll
        for (int i = 0; i < 4; ++i) {
            int lin = tid + i * 256;
            int r = lin >> 3;
            int j = (lin & 7) * 4;
            uint4 w = *reinterpret_cast<const uint4*>(
                Ap + (size_t)(row0 + r) * K + kt * TBK + j);
            *reinterpret_cast<uint2*>(&AsH[r * ASTR + j]) =
                make_uint2(__byte_perm(w.x, w.y, 0x5410u),
                           __byte_perm(w.z, w.w, 0x5410u));
            *reinterpret_cast<uint2*>(&AsL[r * ASTR + j]) =
                make_uint2(__byte_perm(w.x, w.y, 0x7632u),
                           __byte_perm(w.z, w.w, 0x7632u));
        }
#pragma unroll
        for (int i = 0; i < 4; ++i) {
            int lin = tid + i * 256;
            int r = lin >> 5;
            int j = (lin & 31) * 4;
            uint4 w = *reinterpret_cast<const uint4*>(
                Bp + (size_t)(kt * TBK + r) * N + col0 + j);
            *reinterpret_cast<uint2*>(&BsH[r * BSTR + j]) =
                make_uint2(__byte_perm(w.x, w.y, 0x5410u),
                           __byte_perm(w.z, w.w, 0x5410u));
            *reinterpret_cast<uint2*>(&BsL[r * BSTR + j]) =
                make_uint2(__byte_perm(w.x, w.y, 0x7632u),
                           __byte_perm(w.z, w.w, 0x7632u));
        }
        __syncthreads();

#pragma unroll
        for (int ks = 0; ks < 2; ++ks) {
            unsigned aH[2][4], aL[2][4];
#pragma unroll
            for (int mt = 0; mt < 2; ++mt) {
                int r = warp_m * 32 + mt * 16 + (lane & 15);
                int c = ks * 16 + (lane >> 4) * 8;
                ldsm_x4(aH[mt][0], aH[mt][1], aH[mt][2], aH[mt][3],
                        cvta_s(&AsH[r * ASTR + c]));
                ldsm_x4(aL[mt][0], aL[mt][1], aL[mt][2], aL[mt][3],
                        cvta_s(&AsL[r * ASTR + c]));
            }
#pragma unroll
            for (int nt = 0; nt < 8; ++nt) {
                int kr = ks * 16 + (lane & 15);
                int nc = warp_n * 64 + nt * 8;
                unsigned bH[2], bL[2];
                ldsm_x2_t(bH[0], bH[1], cvta_s(&BsH[kr * BSTR + nc]));
                ldsm_x2_t(bL[0], bL[1], cvta_s(&BsL[kr * BSTR + nc]));
#pragma unroll
                for (int mt = 0; mt < 2; ++mt) {
                    mma_bf16(acc[mt][nt], aH[mt], bH);
                    mma_bf16(acc[mt][nt], aL[mt], bH);
                    mma_bf16(acc[mt][nt], aH[mt], bL);
                }
            }
        }
    }

    const int g = lane >> 2, tig = lane & 3;
#pragma unroll
    for (int mt = 0; mt < 2; ++mt) {
        int r0 = row0 + warp_m * 32 + mt * 16 + g;
#pragma unroll
        for (int nt = 0; nt < 8; ++nt) {
            int c0 = col0 + warp_n * 64 + nt * 8 + 2 * tig;
            *reinterpret_cast<float2*>(C + (size_t)r0 * N + c0) =
                make_float2(acc[mt][nt][0], acc[mt][nt][1]);
            *reinterpret_cast<float2*>(C + (size_t)(r0 + 8) * N + c0) =
                make_float2(acc[mt][nt][2], acc[mt][nt][3]);
        }
    }
}

// ---------------------------------------------------------------------------
// Fused LoRA-first stage: ONE launch covers all 4 small GEMMs via blockIdx.z.
// C_z = act_z( (x + (shift(x)-x)*maa_z) @ B_z ), packed split-bf16 output.
// BM=64, BN=64, TM=TN=4, 256 threads. grid = (2, 256, 4); inactive x-tiles
// (N_z <= 64) exit early (uniform per-CTA, before any __syncthreads).
// ---------------------------------------------------------------------------
__global__ void __launch_bounds__(256) lora1_kernel(
    const float* __restrict__ x,
    const float* m0, const float* m1, const float* m2, const float* m3,
    const float* b0, const float* b1, const float* b2, const float* b3,
    unsigned* c0, unsigned* c1, unsigned* c2, unsigned* c3)
{
    const int z = blockIdx.z;
    const float* Mv; const float* B; unsigned* Cp; int N; int act;
    if (z == 0)      { Mv = m0; B = b0; Cp = c0; N = 64;  act = 1; }
    else if (z == 1) { Mv = m1; B = b1; Cp = c1; N = 64;  act = 0; }
    else if (z == 2) { Mv = m2; B = b2; Cp = c2; N = 128; act = 2; }
    else             { Mv = m3; B = b3; Cp = c3; N = 32;  act = 0; }

    const int col0 = blockIdx.x * 64;
    if (col0 >= N) return;
    const int row0 = blockIdx.y * 64;
    const int K = NC;

    __shared__ float As[8][64];
    __shared__ float Bs[8][64];

    const int tid  = threadIdx.x;
    const int trow = tid / 16;       // 0..15 -> 4 rows each
    const int tcol = tid % 16;       // 0..15 -> 4 cols each

    float acc[4][4];
#pragma unroll
    for (int i = 0; i < 4; ++i)
#pragma unroll
        for (int j = 0; j < 4; ++j) acc[i][j] = 0.f;

    for (int kt = 0; kt < K/8; ++kt) {
        const int k0 = kt * 8;
        // A tile 64x8 with fused mix (128 float4 chunks); B tile 8x64
        if (tid < 128) {
            int r  = tid >> 1;
            int kk = (tid & 1) * 4;
            int grow = row0 + r;
            const float* ap = x + (size_t)grow * K + k0 + kk;
            float4 v = *reinterpret_cast<const float4*>(ap);
            float4 m = *reinterpret_cast<const float4*>(Mv + k0 + kk);
            float4 xp = make_float4(0.f,0.f,0.f,0.f);
            if ((grow & (NT-1)) != 0)
                xp = *reinterpret_cast<const float4*>(ap - K);
            v.x += (xp.x - v.x) * m.x;
            v.y += (xp.y - v.y) * m.y;
            v.z += (xp.z - v.z) * m.z;
            v.w += (xp.w - v.w) * m.w;
            As[kk+0][r] = v.x; As[kk+1][r] = v.y;
            As[kk+2][r] = v.z; As[kk+3][r] = v.w;
        } else {
            int lin = tid - 128;     // 0..127 -> 8 rows x 16 col-chunks
            int r  = lin >> 4;
            int cc = (lin & 15) * 4;
            int gc = col0 + cc;
            float4 v = make_float4(0.f,0.f,0.f,0.f);
            if (gc < N) v = *reinterpret_cast<const float4*>(
                B + (size_t)(k0 + r) * N + gc);
            *reinterpret_cast<float4*>(&Bs[r][cc]) = v;
        }
        __syncthreads();

#pragma unroll
        for (int k = 0; k < 8; ++k) {
            float ar[4], br[4];
            float4 ta = *reinterpret_cast<const float4*>(&As[k][trow*4]);
            ar[0]=ta.x; ar[1]=ta.y; ar[2]=ta.z; ar[3]=ta.w;
            float4 tb = *reinterpret_cast<const float4*>(&Bs[k][tcol*4]);
            br[0]=tb.x; br[1]=tb.y; br[2]=tb.z; br[3]=tb.w;
#pragma unroll
            for (int i = 0; i < 4; ++i)
#pragma unroll
                for (int j = 0; j < 4; ++j)
                    acc[i][j] += ar[i] * br[j];
        }
        __syncthreads();
    }

    // epilogue: act + split-pack
#pragma unroll
    for (int i = 0; i < 4; ++i) {
        size_t gr = (size_t)(row0 + trow*4 + i);
        int gc = col0 + tcol*4;
        if (gc < N) {
            uint4 u;
            float vv[4];
#pragma unroll
            for (int j = 0; j < 4; ++j) {
                float v = acc[i][j];
                if (act == 1) v = tanhf(v);
                else if (act == 2) v = 1.f / (1.f + expf(-v));
                vv[j] = v;
            }
            u.x = packsplit(vv[0]); u.y = packsplit(vv[1]);
            u.z = packsplit(vv[2]); u.w = packsplit(vv[3]);
            *reinterpret_cast<uint4*>(Cp + gr * N + gc) = u;
        }
    }
}

// ---------------------------------------------------------------------------
// Pre-recurrence fusion (warp = one (b,t,h) head; lane = 2 channels).
// IN-PLACE: Wd over Wp, K2 over Kr, Vf over Vr, AA over Ap, BB over Vm.
// ---------------------------------------------------------------------------
__device__ __forceinline__ float warp_sum(float v) {
#pragma unroll
    for (int o = 16; o > 0; o >>= 1) v += __shfl_xor_sync(0xffffffffu, v, o);
    return v;
}
__device__ __forceinline__ float sigmoidf_(float v) { return 1.f / (1.f + expf(-v)); }
__device__ __forceinline__ float softplusf_(float z) {
    return fmaxf(z, 0.f) + log1pf(expf(-fabsf(z)));
}

__global__ void fuse_pre_kernel(
    const float* v0,
    const float* td, const float* taa, const float* tmv,
    const float* tkkk, const float* tma,
    float* bK, float* bV, float* bW, float* bA, float* bM)
{
    int gw = blockIdx.x * (blockDim.x >> 5) + (threadIdx.x >> 5);
    if (gw >= NBT * NH) return;
    int lane = threadIdx.x & 31;
    int h  = gw & (NH - 1);
    int bt = gw >> 4;
    size_t idx = (size_t)bt * NC + h * 64 + lane * 2;
    int c = h * 64 + lane * 2;

    float2 kr  = *reinterpret_cast<const float2*>(bK + idx);
    float2 vr  = *reinterpret_cast<const float2*>(bV + idx);
    float2 wp  = *reinterpret_cast<const float2*>(bW + idx);
    float2 ap  = *reinterpret_cast<const float2*>(bA + idx);
    float2 vm  = *reinterpret_cast<const float2*>(bM + idx);
    float2 v0v = *reinterpret_cast<const float2*>(v0 + idx);
    float2 tdv = *reinterpret_cast<const float2*>(td + c);
    float2 tav = *reinterpret_cast<const float2*>(taa + c);
    float2 tmvv= *reinterpret_cast<const float2*>(tmv + c);
    float2 tkv = *reinterpret_cast<const float2*>(tkkk + c);
    float2 tmav= *reinterpret_cast<const float2*>(tma + c);

    float u0 = tdv.x + wp.x, u1 = tdv.y + wp.y;
    float w0 = -softplusf_(-u0) - 0.5f, w1 = -softplusf_(-u1) - 0.5f;
    float2 wd = make_float2(expf(-expf(w0)), expf(-expf(w1)));
    float as0 = sigmoidf_(tav.x + ap.x), as1 = sigmoidf_(tav.y + ap.y);
    float vs0 = sigmoidf_(tmvv.x + vm.x), vs1 = sigmoidf_(tmvv.y + vm.y);
    float2 vf = make_float2(vr.x + (v0v.x - vr.x) * vs0,
                            vr.y + (v0v.y - vr.y) * vs1);
    float kt0 = kr.x * tkv.x, kt1 = kr.y * tkv.y;
    float ss = warp_sum(kt0*kt0 + kt1*kt1);
    float inv = 1.f / fmaxf(sqrtf(ss), 1e-12f);
    float kk0 = kt0 * inv, kk1 = kt1 * inv;

    float2 aa = make_float2(-kk0, -kk1);
    float2 bb = make_float2(kk0 * as0, kk1 * as1);
    float2 k2 = make_float2(kr.x * (1.f + (as0 - 1.f) * tmav.x),
                            kr.y * (1.f + (as1 - 1.f) * tmav.y));

    *reinterpret_cast<float2*>(bW + idx) = wd;
    *reinterpret_cast<float2*>(bK + idx) = k2;
    *reinterpret_cast<float2*>(bV + idx) = vf;
    *reinterpret_cast<float2*>(bA + idx) = aa;
    *reinterpret_cast<float2*>(bM + idx) = bb;
}

// ---------------------------------------------------------------------------
// RWKV7 recurrence. One CTA per (b,h); 128 threads; state in registers.
// ---------------------------------------------------------------------------
__global__ void __launch_bounds__(128) wkv7_kernel(
    const float* __restrict__ R,  const float* __restrict__ Wd,
    const float* __restrict__ K2, const float* __restrict__ V,
    const float* __restrict__ AA, const float* __restrict__ BB,
    float* __restrict__ Y)
{
    const int bh = blockIdx.x;
    const int b = bh / NH, h = bh % NH;
    const int tid = threadIdx.x;
    const int i = tid >> 1;
    const int halfc = tid & 1;
    const int lhalf = tid >> 6;
    const int lj = tid & 63;

    __shared__ float sm[2][6][64];
    float st[32];
#pragma unroll
    for (int j = 0; j < 32; ++j) st[j] = 0.f;

    const size_t base = (size_t)b * NT * NC + (size_t)h * 64;

    if (lhalf == 0) {
        sm[0][0][lj] = R [base + lj];
        sm[0][2][lj] = K2[base + lj];
        sm[0][4][lj] = AA[base + lj];
    } else {
        sm[0][1][lj] = Wd[base + lj];
        sm[0][3][lj] = V [base + lj];
        sm[0][5][lj] = BB[base + lj];
    }

    const int jb = halfc * 32;
    for (int t = 0; t < NT; ++t) {
        __syncthreads();
        const int cur = t & 1;
        if (t + 1 < NT) {
            const size_t nb = base + (size_t)(t + 1) * NC;
            const int nxt = cur ^ 1;
            if (lhalf == 0) {
                sm[nxt][0][lj] = R [nb + lj];
                sm[nxt][2][lj] = K2[nb + lj];
                sm[nxt][4][lj] = AA[nb + lj];
            } else {
                sm[nxt][1][lj] = Wd[nb + lj];
                sm[nxt][3][lj] = V [nb + lj];
                sm[nxt][5][lj] = BB[nb + lj];
            }
        }
        const float4* rs4 = reinterpret_cast<const float4*>(&sm[cur][0][jb]);
        const float4* ws4 = reinterpret_cast<const float4*>(&sm[cur][1][jb]);
        const float4* ks4 = reinterpret_cast<const float4*>(&sm[cur][2][jb]);
        const float4* as4 = reinterpret_cast<const float4*>(&sm[cur][4][jb]);
        const float4* bs4 = reinterpret_cast<const float4*>(&sm[cur][5][jb]);
        const float vi = sm[cur][3][i];

        float sa = 0.f;
#pragma unroll
        for (int j4 = 0; j4 < 8; ++j4) {
            float4 a = as4[j4];
            sa += st[4*j4+0]*a.x + st[4*j4+1]*a.y + st[4*j4+2]*a.z + st[4*j4+3]*a.w;
        }
        sa += __shfl_xor_sync(0xffffffffu, sa, 1);

        float out = 0.f;
#pragma unroll
        for (int j4 = 0; j4 < 8; ++j4) {
            float4 w = ws4[j4], bb = bs4[j4], kk = ks4[j4], rr = rs4[j4];
            float s0 = st[4*j4+0]*w.x + sa*bb.x + vi*kk.x;
            float s1 = st[4*j4+1]*w.y + sa*bb.y + vi*kk.y;
            float s2 = st[4*j4+2]*w.z + sa*bb.z + vi*kk.z;
            float s3 = st[4*j4+3]*w.w + sa*bb.w + vi*kk.w;
            st[4*j4+0] = s0; st[4*j4+1] = s1; st[4*j4+2] = s2; st[4*j4+3] = s3;
            out += s0*rr.x + s1*rr.y + s2*rr.z + s3*rr.w;
        }
        out += __shfl_xor_sync(0xffffffffu, out, 1);
        if (halfc == 0) Y[base + (size_t)t * NC + i] = out;
    }
}

// ---------------------------------------------------------------------------
// Post: per-head GroupNorm + rkv bonus + gate -> packed split-bf16 Y2
// ---------------------------------------------------------------------------
__global__ void post_kernel(
    const float* __restrict__ Y,  const float* __restrict__ R,
    const float* __restrict__ K2, const float* __restrict__ Vf,
    const float* __restrict__ G,  const float* __restrict__ fa,
    const float* __restrict__ lnw, const float* __restrict__ lnb,
    unsigned* __restrict__ Y2p)
{
    int gw = blockIdx.x * (blockDim.x >> 5) + (threadIdx.x >> 5);
    if (gw >= NBT * NH) return;
    int lane = threadIdx.x & 31;
    int h  = gw & (NH - 1);
    int bt = gw >> 4;
    size_t idx = (size_t)bt * NC + h * 64 + lane * 2;
    int c = h * 64 + lane * 2;

    float2 y  = *reinterpret_cast<const float2*>(Y  + idx);
    float2 r2 = *reinterpret_cast<const float2*>(R  + idx);
    float2 k2 = *reinterpret_cast<const float2*>(K2 + idx);
    float2 vf = *reinterpret_cast<const float2*>(Vf + idx);
    float2 g2 = *reinterpret_cast<const float2*>(G  + idx);
    float2 fav = *reinterpret_cast<const float2*>(fa + c);
    float2 lw = *reinterpret_cast<const float2*>(lnw + c);
    float2 lb = *reinterpret_cast<const float2*>(lnb + c);

    float s1 = warp_sum(y.x + y.y);
    float s2 = warp_sum(y.x*y.x + y.y*y.y);
    float mu  = s1 * (1.f / 64.f);
    float var = s2 * (1.f / 64.f) - mu * mu;
    float rs  = rsqrtf(var + 6.4e-4f);

    float srkv = warp_sum(r2.x*k2.x*fav.x + r2.y*k2.y*fav.y);

    float o0 = (((y.x - mu) * rs) * lw.x + lb.x + srkv * vf.x) * g2.x;
    float o1 = (((y.y - mu) * rs) * lw.y + lb.y + srkv * vf.y) * g2.y;
    *reinterpret_cast<uint2*>(Y2p + idx) =
        make_uint2(packsplit(o0), packsplit(o1));
}

// ---------------------------------------------------------------------------
// Host launcher
// ---------------------------------------------------------------------------
extern "C" void kernel_launch(void* const* d_in, const int* in_sizes, int n_in,
                              void* d_out, int out_size)
{
    (void)in_sizes; (void)n_in;
    const float* x     = (const float*)d_in[0];
    const float* v0    = (const float*)d_in[1];
    const float* maa_r = (const float*)d_in[2];
    const float* maa_w = (const float*)d_in[3];
    const float* maa_k = (const float*)d_in[4];
    const float* maa_v = (const float*)d_in[5];
    const float* maa_a = (const float*)d_in[6];
    const float* maa_g = (const float*)d_in[7];
    const float* tdec  = (const float*)d_in[8];
    const float* faaaa = (const float*)d_in[9];
    const float* taaaaa= (const float*)d_in[10];
    const float* dw1   = (const float*)d_in[11];
    const float* dw2   = (const float*)d_in[12];
    const float* aw1   = (const float*)d_in[13];
    const float* aw2   = (const float*)d_in[14];
    const float* gw1   = (const float*)d_in[15];
    const float* gw2   = (const float*)d_in[16];
    const float* mvw1  = (const float*)d_in[17];
    const float* mvw2  = (const float*)d_in[18];
    const float* tmv   = (const float*)d_in[19];
    const float* tkkk  = (const float*)d_in[20];
    const float* tma_  = (const float*)d_in[21];
    const float* W_r   = (const float*)d_in[22];
    const float* W_k   = (const float*)d_in[23];
    const float* W_v   = (const float*)d_in[24];
    const float* W_out = (const float*)d_in[25];
    const float* lnw   = (const float*)d_in[26];
    const float* lnb   = (const float*)d_in[27];
    float* out = (float*)d_out;

    void* q;
    float *p_R,*p_K,*p_V,*p_W,*p_A,*p_M,*p_G,*p_Y;
    unsigned *p_Hw,*p_Ha,*p_Hg,*p_Hv;
    unsigned *p_AxR,*p_AxK,*p_AxV,*p_WbR,*p_WbK,*p_WbV,*p_WbO;
    unsigned *p_W2d,*p_W2a,*p_W2g,*p_W2v;
    cudaGetSymbolAddress(&q, g_bR); p_R = (float*)q;
    cudaGetSymbolAddress(&q, g_bK); p_K = (float*)q;
    cudaGetSymbolAddress(&q, g_bV); p_V = (float*)q;
    cudaGetSymbolAddress(&q, g_bW); p_W = (float*)q;
    cudaGetSymbolAddress(&q, g_bA); p_A = (float*)q;
    cudaGetSymbolAddress(&q, g_bM); p_M = (float*)q;
    cudaGetSymbolAddress(&q, g_bG); p_G = (float*)q;
    cudaGetSymbolAddress(&q, g_bY); p_Y = (float*)q;
    cudaGetSymbolAddress(&q, g_Hw); p_Hw = (unsigned*)q;
    cudaGetSymbolAddress(&q, g_Ha); p_Ha = (unsigned*)q;
    cudaGetSymbolAddress(&q, g_Hg); p_Hg = (unsigned*)q;
    cudaGetSymbolAddress(&q, g_Hv); p_Hv = (unsigned*)q;
    cudaGetSymbolAddress(&q, g_AxR); p_AxR = (unsigned*)q;
    cudaGetSymbolAddress(&q, g_AxK); p_AxK = (unsigned*)q;
    cudaGetSymbolAddress(&q, g_AxV); p_AxV = (unsigned*)q;
    cudaGetSymbolAddress(&q, g_WbR); p_WbR = (unsigned*)q;
    cudaGetSymbolAddress(&q, g_WbK); p_WbK = (unsigned*)q;
    cudaGetSymbolAddress(&q, g_WbV); p_WbV = (unsigned*)q;
    cudaGetSymbolAddress(&q, g_WbO); p_WbO = (unsigned*)q;
    cudaGetSymbolAddress(&q, g_W2d); p_W2d = (unsigned*)q;
    cudaGetSymbolAddress(&q, g_W2a); p_W2a = (unsigned*)q;
    cudaGetSymbolAddress(&q, g_W2g); p_W2g = (unsigned*)q;
    cudaGetSymbolAddress(&q, g_W2v); p_W2v = (unsigned*)q;

    // 1. mix + pack activations; pack the four big weights (launches 1-5)
    mix3_pack_kernel<<<(NBTC/4 + 255)/256, 256>>>(x, maa_r, maa_k, maa_v,
                                                  p_AxR, p_AxK, p_AxV);
    pack_kernel<<<(NC*NC/4 + 255)/256, 256>>>(W_r,   p_WbR, NC*NC/4);
    pack_kernel<<<(NC*NC/4 + 255)/256, 256>>>(W_k,   p_WbK, NC*NC/4);
    pack_kernel<<<(NC*NC/4 + 255)/256, 256>>>(W_v,   p_WbV, NC*NC/4);
    pack_kernel<<<(NC*NC/4 + 255)/256, 256>>>(W_out, p_WbO, NC*NC/4);
    // 2. big projections (launch 6 = gemm R -> profiled by ncu -s 5 -c 1)
    bf16gemm_kernel<<<dim3(NC/TBN, NBT/TBM), 256>>>(p_AxR, p_WbR, p_R, NBT, NC, NC);
    bf16gemm_kernel<<<dim3(NC/TBN, NBT/TBM), 256>>>(p_AxK, p_WbK, p_K, NBT, NC, NC);
    bf16gemm_kernel<<<dim3(NC/TBN, NBT/TBM), 256>>>(p_AxV, p_WbV, p_V, NBT, NC, NC);
    // 3. LoRA second-stage weight packs
    pack_kernel<<<(64*NC/4 + 255)/256, 256>>>(dw2,  p_W2d, 64*NC/4);
    pack_kernel<<<(64*NC/4 + 255)/256, 256>>>(aw2,  p_W2a, 64*NC/4);
    pack_kernel<<<(128*NC/4 + 255)/256, 256>>>(gw2, p_W2g, 128*NC/4);
    pack_kernel<<<(32*NC/4 + 255)/256, 256>>>(mvw2, p_W2v, 32*NC/4);
    // 4. fused LoRA first stage (one launch, 4 GEMMs via blockIdx.z)
    lora1_kernel<<<dim3(2, NBT/64, 4), 256>>>(
        x, maa_w, maa_a, maa_g, maa_v,
        dw1, aw1, gw1, mvw1,
        p_Hw, p_Ha, p_Hg, p_Hv);
    // 5. LoRA second stages on tensor cores
    bf16gemm_kernel<<<dim3(NC/TBN, NBT/TBM), 256>>>(p_Hw, p_W2d, p_W, NBT, NC,  64);
    bf16gemm_kernel<<<dim3(NC/TBN, NBT/TBM), 256>>>(p_Ha, p_W2a, p_A, NBT, NC,  64);
    bf16gemm_kernel<<<dim3(NC/TBN, NBT/TBM), 256>>>(p_Hg, p_W2g, p_G, NBT, NC, 128);
    bf16gemm_kernel<<<dim3(NC/TBN, NBT/TBM), 256>>>(p_Hv, p_W2v, p_M, NBT, NC,  32);
    // 6. pre-recurrence fusion (in-place)
    fuse_pre_kernel<<<(NBT*NH)/8, 256>>>(v0, tdec, taaaaa, tmv, tkkk, tma_,
                                         p_K, p_V, p_W, p_A, p_M);
    // 7. recurrence
    wkv7_kernel<<<NB*NH, 128>>>(p_R, p_W, p_K, p_V, p_A, p_M, p_Y);
    // 8. groupnorm + rkv + gate -> packed Y2 (into AxR scratch)
    post_kernel<<<(NBT*NH)/8, 256>>>(p_Y, p_R, p_K, p_V, p_G, faaaa,
                                     lnw, lnb, p_AxR);
    // 9. output projection
    bf16gemm_kernel<<<dim3(NC/TBN, NBT/TBM), 256>>>(p_AxR, p_WbO, out, NBT, NC, NC);
    // 10. second tuple element: v0 passthrough
    if (out_size >= 2*NBTC) {
        cudaMemcpyAsync(out + NBTC, v0, (size_t)NBTC * sizeof(float),
                        cudaMemcpyDeviceToDevice, 0);
    }
}